// round 10
// baseline (speedup 1.0000x reference)
#include <cuda_runtime.h>
#include <math_constants.h>
#include <cstdint>

// ---------------- static device scratch (no runtime allocation) ----------------
// Branch-concatenated layouts, cumc = {0,64,192,448}, total c = 960.
__device__ __align__(16) float g_K     [64u*196*960];   // [z][196][960]
__device__ __align__(16) float g_Vt    [64u*960*196];   // [z][960][196]
__device__ __align__(16) float g_Qt    [64u*960*196];   // per-branch [64][c][196] regions
__device__ __align__(16) float g_scores[64u*960*960];   // per-branch [64][c][960] regions
__device__ __align__(16) float g_ctx   [64u*960*196];   // per-branch [64][c][196] regions
__device__ __align__(16) float g_ctxm  [16u*196*960];   // per-branch [16][196][c] regions
__device__ float g_invstd [4*64];
__device__ float g_partial[4*64*32*2];
__device__ int   g_rowmaxi[64*960];                     // linear rows: base[br] + z*c + d

__device__ __forceinline__ int f2ord(float f) {
    int i = __float_as_int(f);
    return i >= 0 ? i : i ^ 0x7fffffff;
}
__device__ __forceinline__ float ord2f(int i) {
    return __int_as_float(i >= 0 ? i : i ^ 0x7fffffff);
}

// ---- packed dual-FMA (Blackwell FFMA2): exact fp32 lanewise fma ----
__device__ __forceinline__ unsigned long long dupf(float x) {
    unsigned long long d;
    asm("mov.b64 %0, {%1, %1};" : "=l"(d) : "f"(x));
    return d;
}
__device__ __forceinline__ void ffma2(unsigned long long& c,
                                      unsigned long long a, unsigned long long b) {
    asm("fma.rn.f32x2 %0, %1, %2, %3;" : "=l"(c) : "l"(a), "l"(b), "l"(c));
}

#define BM 128
#define BN 128
#define BK 8
#define PAD 4

// ---------------- job table for merged GEMM launches ------------------------------
struct Jobs {
    const float* A[4]; const float* B[4]; float* C[4];
    long sAh[4], sAb[4], sBh[4], sBb[4], sCh[4], sCb[4];
    int  lda[4], ldb[4], ldc[4], M[4], N[4], K[4];
    float alpha[4];
    int  nx[4];      // tiles along N
    int  bx0[4];     // cumulative blockIdx.x start (unused: INT_MAX)
    int  rmoff[4];   // row-max base (row units)
};

// ---------------------------------------------------------------------------------
// C[M,N] = alpha * A[M,K] * opB  — scalar-pipe SGEMM with packed FFMA2 inner loop.
//   LAYB==0 : B is [N,K] row-major (C = A * B^T)
//   LAYB==1 : B is [K,N] row-major (C = A * B)
// STATS: epilogue row-max atomics + block sum/sumsq partials (InstanceNorm)
// ---------------------------------------------------------------------------------
template<int LAYB, bool STATS>
__device__ __forceinline__ void gemm_core(const Jobs& J, int br, int local, int zz)
{
    __shared__ __align__(16) float As[2][BK][BM + PAD];
    __shared__ __align__(16) float Bs[2][BK][BN + PAD];
    const float* A = J.A[br];
    const float* B = J.B[br];
    float*       C = J.C[br];
    const int lda = J.lda[br], ldb = J.ldb[br], ldc = J.ldc[br];
    const int M = J.M[br], N = J.N[br], K = J.K[br];
    const float alpha = J.alpha[br];
    const int h = zz & 3, bb_ = zz >> 2;
    A += (long)h * J.sAh[br] + (long)bb_ * J.sAb[br];
    B += (long)h * J.sBh[br] + (long)bb_ * J.sBb[br];
    C += (long)h * J.sCh[br] + (long)bb_ * J.sCb[br];
    const int nx = J.nx[br];
    const int row0 = (local / nx) * BM, col0 = (local % nx) * BN;

    const int tid = threadIdx.x;
    const int tx = tid & 15, ty = tid >> 4;

    // A tile loader: 128 rows x 8 k, one float4 per thread
    const int arow  = tid >> 1;
    const int akseg = (tid & 1) * 4;
    const int agr   = row0 + arow;
    // B tile loader
    const int brow  = tid >> 1;          // LAYB==0
    const int bkseg = (tid & 1) * 4;
    const int bkk   = tid >> 5;          // LAYB==1
    const int bn    = (tid & 31) * 4;

    // packed accumulators: pairs along j  (acc[i][j2] = cols {2j2, 2j2+1})
    unsigned long long acc[8][4];
#pragma unroll
    for (int i = 0; i < 8; i++)
#pragma unroll
        for (int j = 0; j < 4; j++) acc[i][j] = 0ull;

    const int KT = (K + BK - 1) / BK;
    float4 av, bv;

    auto loadA = [&](int k0) {
        float4 v = make_float4(0.f, 0.f, 0.f, 0.f);
        int gk = k0 + akseg;
        if (agr < M && gk < K)
            v = *reinterpret_cast<const float4*>(A + (size_t)agr * lda + gk);
        return v;
    };
    auto loadB = [&](int k0) {
        float4 v = make_float4(0.f, 0.f, 0.f, 0.f);
        if (LAYB == 0) {
            int gk = k0 + bkseg, gn = col0 + brow;
            if (gn < N && gk < K)
                v = *reinterpret_cast<const float4*>(B + (size_t)gn * ldb + gk);
        } else {
            int gk = k0 + bkk, gn = col0 + bn;
            if (gk < K && gn < N)
                v = *reinterpret_cast<const float4*>(B + (size_t)gk * ldb + gn);
        }
        return v;
    };
    auto storeS = [&](int s) {
        As[s][akseg + 0][arow] = av.x; As[s][akseg + 1][arow] = av.y;
        As[s][akseg + 2][arow] = av.z; As[s][akseg + 3][arow] = av.w;
        if (LAYB == 0) {
            Bs[s][bkseg + 0][brow] = bv.x; Bs[s][bkseg + 1][brow] = bv.y;
            Bs[s][bkseg + 2][brow] = bv.z; Bs[s][bkseg + 3][brow] = bv.w;
        } else {
            *reinterpret_cast<float4*>(&Bs[s][bkk][bn]) = bv;
        }
    };
    auto compute = [&](int s) {
#pragma unroll
        for (int kk = 0; kk < BK; kk++) {
            float a[8];
            *reinterpret_cast<float4*>(a)     = *reinterpret_cast<const float4*>(&As[s][kk][ty * 8]);
            *reinterpret_cast<float4*>(a + 4) = *reinterpret_cast<const float4*>(&As[s][kk][ty * 8 + 4]);
            ulonglong2 b01 = *reinterpret_cast<const ulonglong2*>(&Bs[s][kk][tx * 8]);
            ulonglong2 b23 = *reinterpret_cast<const ulonglong2*>(&Bs[s][kk][tx * 8 + 4]);
            unsigned long long bp0 = b01.x, bp1 = b01.y, bp2 = b23.x, bp3 = b23.y;
#pragma unroll
            for (int i = 0; i < 8; i++) {
                unsigned long long ad = dupf(a[i]);
                ffma2(acc[i][0], ad, bp0);
                ffma2(acc[i][1], ad, bp1);
                ffma2(acc[i][2], ad, bp2);
                ffma2(acc[i][3], ad, bp3);
            }
        }
    };

    av = loadA(0); bv = loadB(0);
    storeS(0);
    __syncthreads();
    for (int t = 0; t < KT; t++) {
        if (t + 1 < KT) { av = loadA((t + 1) * BK); bv = loadB((t + 1) * BK); }
        compute(t & 1);
        if (t + 1 < KT) storeS((t + 1) & 1);
        __syncthreads();
    }

    // ---- epilogue (row-streamed unpack; identical semantics to round 9) ----
    float lsum = 0.f, lsq = 0.f;
#pragma unroll
    for (int i = 0; i < 8; i++) {
        float r[8];
#pragma unroll
        for (int j2 = 0; j2 < 4; j2++) {
            float2 p = *reinterpret_cast<float2*>(&acc[i][j2]);
            r[2 * j2]     = p.x * alpha;
            r[2 * j2 + 1] = p.y * alpha;
        }
        int gr = row0 + ty * 8 + i;
        if (gr < M) {
            int gc0 = col0 + tx * 8;
            float* cp = C + (size_t)gr * ldc + gc0;
            if (gc0 + 7 < N) {
                *reinterpret_cast<float4*>(cp)     = *reinterpret_cast<float4*>(&r[0]);
                *reinterpret_cast<float4*>(cp + 4) = *reinterpret_cast<float4*>(&r[4]);
            } else {
#pragma unroll
                for (int j = 0; j < 8; j++)
                    if (gc0 + j < N) cp[j] = r[j];
            }
        }
        if (STATS) {
            float rm = -CUDART_INF_F;
#pragma unroll
            for (int j = 0; j < 8; j++) {
                int gc = col0 + tx * 8 + j;
                if (gc < N) {
                    float v = r[j];
                    lsum += v; lsq += v * v;
                    rm = fmaxf(rm, v);
                }
            }
#pragma unroll
            for (int m = 1; m < 16; m <<= 1)
                rm = fmaxf(rm, __shfl_xor_sync(0xffffffffu, rm, m, 16));
            if (tx == 0 && gr < M)
                atomicMax(&g_rowmaxi[J.rmoff[br] + zz * M + gr], f2ord(rm));
        }
    }

    if (STATS) {
        __shared__ float s1[256], s2[256];
        s1[tid] = lsum; s2[tid] = lsq;
        __syncthreads();
        for (int s = 128; s > 0; s >>= 1) {
            if (tid < s) { s1[tid] += s1[tid + s]; s2[tid] += s2[tid + s]; }
            __syncthreads();
        }
        if (tid == 0) {
            int pb = ((br * 64 + zz) * 32 + local) * 2;
            g_partial[pb] = s1[0];
            g_partial[pb + 1] = s2[0];
        }
    }
}

__device__ __forceinline__ int pick_branch(const Jobs& J, int bx) {
    int br = 0;
    if (bx >= J.bx0[1]) br = 1;
    if (bx >= J.bx0[2]) br = 2;
    if (bx >= J.bx0[3]) br = 3;
    return br;
}

__global__ __launch_bounds__(256, 2) void k_gemm_abT(Jobs J) {
    int bx = blockIdx.x, br = pick_branch(J, bx);
    gemm_core<0, false>(J, br, bx - J.bx0[br], blockIdx.z);
}
__global__ __launch_bounds__(256, 2) void k_gemm_ab(Jobs J) {
    int bx = blockIdx.x, br = pick_branch(J, bx);
    gemm_core<1, false>(J, br, bx - J.bx0[br], blockIdx.z);
}
__global__ __launch_bounds__(256, 2) void k_gemm_ab_stats(Jobs J) {
    int bx = blockIdx.x, br = pick_branch(J, bx);
    gemm_core<1, true>(J, br, bx - J.bx0[br], blockIdx.z);
}

// ---------------- small kernels ----------------------------------------------------
__global__ void k_initmax()
{
    int i = blockIdx.x * 256 + threadIdx.x;
    if (i < 64 * 960) g_rowmaxi[i] = 0x80000000;
}

__global__ void k_stats_final()
{
    int t = threadIdx.x;                    // 256 = 4 branches x 64 z
    int br = t >> 6, z = t & 63;
    const int nbk[4] = {8, 8, 16, 32};      // 8 * my tiles per (br,z)
    const int cs[4]  = {64, 128, 256, 512};
    float sum = 0.f, sq = 0.f;
    int base = (br * 64 + z) * 32;
    for (int s = 0; s < nbk[br]; s++) {
        sum += g_partial[(base + s) * 2 + 0];
        sq  += g_partial[(base + s) * 2 + 1];
    }
    float n = (float)cs[br] * 960.f;
    float m = sum / n;
    g_invstd[t] = rsqrtf(sq / n - m * m + 1e-5f);
}

// One block per score row: p <- softmax((p - mean)*invstd) computed as
// exp(p*invstd - max*invstd)/sum (InstanceNorm mean cancels by shift-invariance).
__global__ __launch_bounds__(256) void k_probs()
{
    int idx = blockIdx.x;                   // global row in [0, 61440)
    int br = (idx >= 4096) + (idx >= 12288) + (idx >= 28672);
    const int cs[4]   = {64, 128, 256, 512};
    const int base[4] = {0, 4096, 12288, 28672};
    const long soff[4] = {0, 64L*64*960, 64L*192*960, 64L*448*960};
    int local = idx - base[br];
    int z = local / cs[br];
    float is  = g_invstd[br * 64 + z];
    float off = ord2f(g_rowmaxi[idx]) * is;
    float* p = g_scores + soff[br] + (long)local * 960;

    int t = threadIdx.x;
    bool v3 = (t + 768) < 960;
    float e0 = __expf(p[t]       * is - off);
    float e1 = __expf(p[t + 256] * is - off);
    float e2 = __expf(p[t + 512] * is - off);
    float e3 = v3 ? __expf(p[t + 768] * is - off) : 0.f;

    __shared__ float sh[256];
    sh[t] = e0 + e1 + e2 + e3;
    __syncthreads();
    for (int s = 128; s > 0; s >>= 1) {
        if (t < s) sh[t] += sh[t + s];
        __syncthreads();
    }
    float rinv = 1.f / sh[0];
    p[t]       = e0 * rinv;
    p[t + 256] = e1 * rinv;
    p[t + 512] = e2 * rinv;
    if (v3) p[t + 768] = e3 * rinv;
}

// ctxm[b][n][d] = 0.25 * sum_h ctx[b*4+h][d][n]  (all branches merged via blockIdx.y)
__global__ void k_meanT_all()
{
    __shared__ float t[32][33];
    int by = blockIdx.y;
    int br = (by >= 2) + (by >= 6) + (by >= 14);
    const int cs[4]    = {64, 128, 256, 512};
    const int ybase[4] = {0, 2, 6, 14};
    const long ctxoff[4] = {0, 64L*64*196, 64L*192*196, 64L*448*196};
    const long cmoff[4]  = {0, 16L*196*64, 16L*196*192, 16L*196*448};
    int c = cs[br];
    int b  = blockIdx.z;
    int d0 = (by - ybase[br]) * 32, n0 = blockIdx.x * 32;
    const float* ctx = g_ctx + ctxoff[br];
    float* cm = g_ctxm + cmoff[br];
    int tx = threadIdx.x, ty = threadIdx.y;
    for (int i = ty; i < 32; i += 8) {
        int d = d0 + i, n = n0 + tx;
        float s = 0.f;
        if (n < 196) {
            for (int hh = 0; hh < 4; hh++)
                s += ctx[((size_t)(b * 4 + hh) * c + d) * 196 + n];
        }
        t[i][tx] = 0.25f * s;
    }
    __syncthreads();
    for (int i = ty; i < 32; i += 8) {
        int n = n0 + i, d = d0 + tx;
        if (n < 196) cm[((size_t)b * 196 + n) * c + d] = t[tx][i];
    }
}

// ---------------- launch -------------------------------------------------------------
extern "C" void kernel_launch(void* const* d_in, const int* in_sizes, int n_in,
                              void* d_out, int out_size)
{
    (void)in_sizes; (void)n_in; (void)out_size;
    const float* emb[4]  = {(const float*)d_in[0], (const float*)d_in[1],
                            (const float*)d_in[2], (const float*)d_in[3]};
    const float* emb_all = (const float*)d_in[4];
    const float* Wq[4]   = {(const float*)d_in[5], (const float*)d_in[6],
                            (const float*)d_in[7], (const float*)d_in[8]};
    const float* Wk      = (const float*)d_in[9];
    const float* Wv      = (const float*)d_in[10];
    const float* Wo[4]   = {(const float*)d_in[11], (const float*)d_in[12],
                            (const float*)d_in[13], (const float*)d_in[14]};
    float* out = (float*)d_out;

    float *pK, *pVt, *pQt, *pSc, *pCx, *pCm;
    cudaGetSymbolAddress((void**)&pK,  g_K);
    cudaGetSymbolAddress((void**)&pVt, g_Vt);
    cudaGetSymbolAddress((void**)&pQt, g_Qt);
    cudaGetSymbolAddress((void**)&pSc, g_scores);
    cudaGetSymbolAddress((void**)&pCx, g_ctx);
    cudaGetSymbolAddress((void**)&pCm, g_ctxm);

    const int   Cs[4]    = {64, 128, 256, 512};
    const int   cumc[4]  = {0, 64, 192, 448};
    const int   my[4]    = {1, 1, 2, 4};
    const int   rmbase[4]= {0, 4096, 12288, 28672};
    const int   offs[4]  = {0, 16*196*64, 16*196*(64+128), 16*196*(64+128+256)};
    const float SCALE    = 0.03227486121839514f;   // 1/sqrt(960)
    const int   IMAXI    = 0x7fffffff;

    k_initmax<<<(64 * 960 + 255) / 256, 256>>>();

    // ---- merged K/Vt projections: 2 jobs ----
    {
        Jobs J = {};
        // job0: K[z][196][960] = emb_all[b] * Wk[h]^T
        J.A[0]=emb_all; J.sAh[0]=0;        J.sAb[0]=196L*960; J.lda[0]=960;
        J.B[0]=Wk;      J.sBh[0]=960L*960; J.sBb[0]=0;        J.ldb[0]=960;
        J.C[0]=pK;      J.sCh[0]=196L*960; J.sCb[0]=4L*196*960; J.ldc[0]=960;
        J.M[0]=196; J.N[0]=960; J.K[0]=960; J.alpha[0]=1.f; J.nx[0]=8; J.bx0[0]=0;
        // job1: Vt[z][960][196] = Wv[h] * emb_all[b]^T
        J.A[1]=Wv;      J.sAh[1]=960L*960; J.sAb[1]=0;        J.lda[1]=960;
        J.B[1]=emb_all; J.sBh[1]=0;        J.sBb[1]=196L*960; J.ldb[1]=960;
        J.C[1]=pVt;     J.sCh[1]=960L*196; J.sCb[1]=4L*960*196; J.ldc[1]=196;
        J.M[1]=960; J.N[1]=196; J.K[1]=960; J.alpha[1]=1.f; J.nx[1]=2; J.bx0[1]=16;
        J.bx0[2]=IMAXI; J.bx0[3]=IMAXI;
        k_gemm_abT<<<dim3(32, 1, 64), 256>>>(J);
    }

    // ---- merged Qt projections (4 jobs) ----
    {
        Jobs J = {};
        int bx = 0;
        for (int br = 0; br < 4; br++) {
            long c = Cs[br];
            J.A[br]=Wq[br];  J.sAh[br]=c*c;     J.sAb[br]=0;         J.lda[br]=(int)c;
            J.B[br]=emb[br]; J.sBh[br]=0;       J.sBb[br]=196L*c;    J.ldb[br]=(int)c;
            J.C[br]=pQt + 64L*196*cumc[br];
            J.sCh[br]=c*196; J.sCb[br]=4L*c*196; J.ldc[br]=196;
            J.M[br]=(int)c; J.N[br]=196; J.K[br]=(int)c; J.alpha[br]=1.f;
            J.nx[br]=2; J.bx0[br]=bx; bx += 2 * my[br];
        }
        k_gemm_abT<<<dim3(16, 1, 64), 256>>>(J);
    }

    // ---- merged scores GEMM + stats epilogue (4 jobs) ----
    {
        Jobs J = {};
        int bx = 0;
        for (int br = 0; br < 4; br++) {
            long c = Cs[br];
            J.A[br]=pQt + 64L*196*cumc[br];
            J.sAh[br]=c*196;    J.sAb[br]=4L*c*196;    J.lda[br]=196;
            J.B[br]=pK; J.sBh[br]=196L*960; J.sBb[br]=4L*196*960; J.ldb[br]=960;
            J.C[br]=pSc + 64L*960*cumc[br];
            J.sCh[br]=c*960;    J.sCb[br]=4L*c*960;    J.ldc[br]=960;
            J.M[br]=(int)c; J.N[br]=960; J.K[br]=196; J.alpha[br]=SCALE;
            J.nx[br]=8; J.bx0[br]=bx; J.rmoff[br]=rmbase[br]; bx += 8 * my[br];
        }
        k_gemm_ab_stats<<<dim3(64, 1, 64), 256>>>(J);
    }

    k_stats_final<<<1, 256>>>();
    k_probs<<<61440, 256>>>();

    // ---- merged ctx GEMM (4 jobs, plain — probs already normalized) ----
    {
        Jobs J = {};
        int bx = 0;
        for (int br = 0; br < 4; br++) {
            long c = Cs[br];
            J.A[br]=pSc + 64L*960*cumc[br];
            J.sAh[br]=c*960;    J.sAb[br]=4L*c*960;    J.lda[br]=960;
            J.B[br]=pVt; J.sBh[br]=960L*196; J.sBb[br]=4L*960*196; J.ldb[br]=196;
            J.C[br]=pCx + 64L*196*cumc[br];
            J.sCh[br]=c*196;    J.sCb[br]=4L*c*196;    J.ldc[br]=196;
            J.M[br]=(int)c; J.N[br]=196; J.K[br]=960; J.alpha[br]=1.f;
            J.nx[br]=2; J.bx0[br]=bx; bx += 2 * my[br];
        }
        k_gemm_ab<<<dim3(16, 1, 64), 256>>>(J);
    }

    k_meanT_all<<<dim3(7, 30, 16), dim3(32, 8)>>>();

    // ---- merged output projections (4 jobs, z=1) ----
    {
        Jobs J = {};
        int bx = 0;
        for (int br = 0; br < 4; br++) {
            long c = Cs[br];
            J.A[br]=pCm + 16L*196*cumc[br];
            J.sAh[br]=0; J.sAb[br]=0; J.lda[br]=(int)c;
            J.B[br]=Wo[br]; J.sBh[br]=0; J.sBb[br]=0; J.ldb[br]=(int)c;
            J.C[br]=out + offs[br]; J.sCh[br]=0; J.sCb[br]=0; J.ldc[br]=(int)c;
            J.M[br]=16*196; J.N[br]=(int)c; J.K[br]=(int)c; J.alpha[br]=1.f;
            int nxo = (Cs[br] + 127) / 128;
            J.nx[br]=nxo; J.bx0[br]=bx; bx += nxo * 25;
        }
        k_gemm_abT<<<dim3(200, 1, 1), 256>>>(J);
    }
}

// round 11
// speedup vs baseline: 1.2123x; 1.2123x over previous
#include <cuda_runtime.h>
#include <math_constants.h>
#include <cstdint>

// ---------------- static device scratch (no runtime allocation) ----------------
// Flat-row layouts: 3136 = 16 batches x 196 tokens. cumc = {0,64,192,448}.
__device__ __align__(16) float g_K     [4u*3136*960];    // [h][3136][960]
__device__ __align__(16) float g_V     [4u*3136*960];    // [h][3136][960]
__device__ __align__(16) float g_Q     [4u*3136*960];    // per-branch [4][3136][c] regions
__device__ __align__(16) float g_scores[64u*960*960];    // per-branch [64z][c][960] regions
__device__ __align__(16) float g_ctx   [64u*960*196];    // per-branch [64z][c][196] regions
__device__ __align__(16) float g_ctxm  [16u*196*960];    // per-branch [16][196][c] regions
__device__ float g_invstd [4*64];
__device__ float g_partial[4*64*32*2];
__device__ int   g_rowmaxi[64*960];                      // rows: rmbase[br] + z*c + d

__device__ __forceinline__ int f2ord(float f) {
    int i = __float_as_int(f);
    return i >= 0 ? i : i ^ 0x7fffffff;
}
__device__ __forceinline__ float ord2f(int i) {
    return __int_as_float(i >= 0 ? i : i ^ 0x7fffffff);
}

#define BM 128
#define BN 128
#define BK 8
#define PAD 4
#define NJ 8

// ---------------- job table for merged GEMM launches ------------------------------
struct Jobs {
    const float* A[NJ]; const float* B[NJ]; float* C[NJ];
    long sAh[NJ], sAb[NJ], sBh[NJ], sBb[NJ], sCh[NJ], sCb[NJ];
    int  lda[NJ], ldb[NJ], ldc[NJ], M[NJ], N[NJ], K[NJ];
    float alpha[NJ];
    int  nx[NJ];      // tiles along N
    int  bx0[NJ];     // cumulative blockIdx.x start (unused: INT_MAX)
    int  rmoff[NJ];   // row-max base (row units)
};

// ---------------------------------------------------------------------------------
// C[M,N] = alpha * opA * opB   — round-9 proven scalar SGEMM core + A^T path.
//   LAYA==0 : A is [M,K] row-major          LAYA==1 : A is [K,M] row-major
//   LAYB==0 : B is [N,K] row-major (B^T)    LAYB==1 : B is [K,N] row-major
// STATS: epilogue row-max atomics + block sum/sumsq partials (InstanceNorm)
// ---------------------------------------------------------------------------------
template<int LAYA, int LAYB, bool STATS>
__device__ __forceinline__ void gemm_core(const Jobs& J, int br, int local, int zz)
{
    __shared__ float As[BK][BM + PAD];
    __shared__ float Bs[BK][BN + PAD];
    const float* A = J.A[br];
    const float* B = J.B[br];
    float*       C = J.C[br];
    const int lda = J.lda[br], ldb = J.ldb[br], ldc = J.ldc[br];
    const int M = J.M[br], N = J.N[br], K = J.K[br];
    const float alpha = J.alpha[br];
    const int h = zz & 3, bb_ = zz >> 2;
    A += (long)h * J.sAh[br] + (long)bb_ * J.sAb[br];
    B += (long)h * J.sBh[br] + (long)bb_ * J.sBb[br];
    C += (long)h * J.sCh[br] + (long)bb_ * J.sCb[br];
    const int nx = J.nx[br];
    const int row0 = (local / nx) * BM, col0 = (local % nx) * BN;

    const int tid = threadIdx.x;
    const int tx = tid & 15, ty = tid >> 4;

    // A tile loader
    const int arow  = tid >> 1;          // LAYA==0: tile row (m)
    const int akseg = (tid & 1) * 4;
    const int agr   = row0 + arow;
    const int akk   = tid >> 5;          // LAYA==1: tile row (k)
    const int am    = (tid & 31) * 4;
    // B tile loader
    const int brow  = tid >> 1;          // LAYB==0
    const int bkseg = (tid & 1) * 4;
    const int bkk   = tid >> 5;          // LAYB==1
    const int bn    = (tid & 31) * 4;

    float acc[8][8];
#pragma unroll
    for (int i = 0; i < 8; i++)
#pragma unroll
        for (int j = 0; j < 8; j++) acc[i][j] = 0.f;

    const int KT = (K + BK - 1) / BK;
    float4 av, bv;

    auto loadA = [&](int k0) {
        float4 v = make_float4(0.f, 0.f, 0.f, 0.f);
        if (LAYA == 0) {
            int gk = k0 + akseg;
            if (agr < M && gk < K)
                v = *reinterpret_cast<const float4*>(A + (size_t)agr * lda + gk);
        } else {
            int gk = k0 + akk, gm = row0 + am;
            if (gk < K && gm < M)
                v = *reinterpret_cast<const float4*>(A + (size_t)gk * lda + gm);
        }
        return v;
    };
    auto loadB = [&](int k0) {
        float4 v = make_float4(0.f, 0.f, 0.f, 0.f);
        if (LAYB == 0) {
            int gk = k0 + bkseg, gn = col0 + brow;
            if (gn < N && gk < K)
                v = *reinterpret_cast<const float4*>(B + (size_t)gn * ldb + gk);
        } else {
            int gk = k0 + bkk, gn = col0 + bn;
            if (gk < K && gn < N)
                v = *reinterpret_cast<const float4*>(B + (size_t)gk * ldb + gn);
        }
        return v;
    };
    auto storeS = [&]() {
        if (LAYA == 0) {
            As[akseg + 0][arow] = av.x; As[akseg + 1][arow] = av.y;
            As[akseg + 2][arow] = av.z; As[akseg + 3][arow] = av.w;
        } else {
            *reinterpret_cast<float4*>(&As[akk][am]) = av;
        }
        if (LAYB == 0) {
            Bs[bkseg + 0][brow] = bv.x; Bs[bkseg + 1][brow] = bv.y;
            Bs[bkseg + 2][brow] = bv.z; Bs[bkseg + 3][brow] = bv.w;
        } else {
            *reinterpret_cast<float4*>(&Bs[bkk][bn]) = bv;
        }
    };
    auto compute = [&]() {
#pragma unroll
        for (int kk = 0; kk < BK; kk++) {
            float a[8], bq[8];
            *reinterpret_cast<float4*>(a)      = *reinterpret_cast<const float4*>(&As[kk][ty * 8]);
            *reinterpret_cast<float4*>(a + 4)  = *reinterpret_cast<const float4*>(&As[kk][ty * 8 + 4]);
            *reinterpret_cast<float4*>(bq)     = *reinterpret_cast<const float4*>(&Bs[kk][tx * 8]);
            *reinterpret_cast<float4*>(bq + 4) = *reinterpret_cast<const float4*>(&Bs[kk][tx * 8 + 4]);
#pragma unroll
            for (int i = 0; i < 8; i++)
#pragma unroll
                for (int j = 0; j < 8; j++)
                    acc[i][j] = fmaf(a[i], bq[j], acc[i][j]);
        }
    };

    av = loadA(0); bv = loadB(0);
    storeS();
    __syncthreads();
    for (int t = 1; t < KT; t++) {
        av = loadA(t * BK); bv = loadB(t * BK);
        compute();
        __syncthreads();
        storeS();
        __syncthreads();
    }
    compute();

#pragma unroll
    for (int i = 0; i < 8; i++)
#pragma unroll
        for (int j = 0; j < 8; j++) acc[i][j] *= alpha;

#pragma unroll
    for (int i = 0; i < 8; i++) {
        int gr = row0 + ty * 8 + i;
        if (gr >= M) continue;
        int gc0 = col0 + tx * 8;
        float* cp = C + (size_t)gr * ldc + gc0;
        if (gc0 + 7 < N) {
            *reinterpret_cast<float4*>(cp)     = *reinterpret_cast<float4*>(&acc[i][0]);
            *reinterpret_cast<float4*>(cp + 4) = *reinterpret_cast<float4*>(&acc[i][4]);
        } else {
#pragma unroll
            for (int j = 0; j < 8; j++)
                if (gc0 + j < N) cp[j] = acc[i][j];
        }
    }

    if (STATS) {
        float lsum = 0.f, lsq = 0.f;
#pragma unroll
        for (int i = 0; i < 8; i++) {
            float rm = -CUDART_INF_F;
            int gr = row0 + ty * 8 + i;
#pragma unroll
            for (int j = 0; j < 8; j++) {
                int gc = col0 + tx * 8 + j;
                if (gc < N) {
                    float v = acc[i][j];
                    lsum += v; lsq += v * v;
                    rm = fmaxf(rm, v);
                }
            }
#pragma unroll
            for (int m = 1; m < 16; m <<= 1)
                rm = fmaxf(rm, __shfl_xor_sync(0xffffffffu, rm, m, 16));
            if (tx == 0 && gr < M)
                atomicMax(&g_rowmaxi[J.rmoff[br] + zz * M + gr], f2ord(rm));
        }
        __shared__ float s1[256], s2[256];
        s1[tid] = lsum; s2[tid] = lsq;
        __syncthreads();
        for (int s = 128; s > 0; s >>= 1) {
            if (tid < s) { s1[tid] += s1[tid + s]; s2[tid] += s2[tid + s]; }
            __syncthreads();
        }
        if (tid == 0) {
            int pb = ((br * 64 + zz) * 32 + local) * 2;
            g_partial[pb] = s1[0];
            g_partial[pb + 1] = s2[0];
        }
    }
}

__device__ __forceinline__ int pick_branch(const Jobs& J, int bx) {
    int br = 0;
#pragma unroll
    for (int i = 1; i < NJ; i++)
        if (bx >= J.bx0[i]) br = i;
    return br;
}

__global__ __launch_bounds__(256, 2) void k_gemm_abT(Jobs J) {
    int bx = blockIdx.x, br = pick_branch(J, bx);
    gemm_core<0, 0, false>(J, br, bx - J.bx0[br], blockIdx.z);
}
__global__ __launch_bounds__(256, 2) void k_gemm_aTb_stats(Jobs J) {
    int bx = blockIdx.x, br = pick_branch(J, bx);
    gemm_core<1, 1, true>(J, br, bx - J.bx0[br], blockIdx.z);
}

// ---------------- small kernels ----------------------------------------------------
__global__ void k_initmax()
{
    int i = blockIdx.x * 256 + threadIdx.x;
    if (i < 64 * 960) g_rowmaxi[i] = 0x80000000;
}

__global__ void k_stats_final()
{
    int t = threadIdx.x;                    // 256 = 4 branches x 64 z
    int br = t >> 6, z = t & 63;
    const int nbk[4] = {8, 8, 16, 32};      // 8 * my blocks per (br,z)
    const int cs[4]  = {64, 128, 256, 512};
    float sum = 0.f, sq = 0.f;
    int base = (br * 64 + z) * 32;
    for (int s = 0; s < nbk[br]; s++) {
        sum += g_partial[(base + s) * 2 + 0];
        sq  += g_partial[(base + s) * 2 + 1];
    }
    float n = (float)cs[br] * 960.f;
    float m = sum / n;
    g_invstd[t] = rsqrtf(sq / n - m * m + 1e-5f);
}

// One block per score row: p <- softmax((p - mean)*invstd) computed as
// exp(p*invstd - max*invstd)/sum (InstanceNorm mean cancels by shift-invariance).
__global__ __launch_bounds__(256) void k_probs()
{
    int idx = blockIdx.x;                   // global row in [0, 61440)
    int br = (idx >= 4096) + (idx >= 12288) + (idx >= 28672);
    const int cs[4]   = {64, 128, 256, 512};
    const int base[4] = {0, 4096, 12288, 28672};
    const long soff[4] = {0, 64L*64*960, 64L*192*960, 64L*448*960};
    int local = idx - base[br];
    int z = local / cs[br];
    float is  = g_invstd[br * 64 + z];
    float off = ord2f(g_rowmaxi[idx]) * is;
    float* p = g_scores + soff[br] + (long)local * 960;

    int t = threadIdx.x;
    bool v3 = (t + 768) < 960;
    float e0 = __expf(p[t]       * is - off);
    float e1 = __expf(p[t + 256] * is - off);
    float e2 = __expf(p[t + 512] * is - off);
    float e3 = v3 ? __expf(p[t + 768] * is - off) : 0.f;

    __shared__ float sh[256];
    sh[t] = e0 + e1 + e2 + e3;
    __syncthreads();
    for (int s = 128; s > 0; s >>= 1) {
        if (t < s) sh[t] += sh[t + s];
        __syncthreads();
    }
    float rinv = 1.f / sh[0];
    p[t]       = e0 * rinv;
    p[t + 256] = e1 * rinv;
    p[t + 512] = e2 * rinv;
    if (v3) p[t + 768] = e3 * rinv;
}

// ctxm[b][n][d] = 0.25 * sum_h ctx[b*4+h][d][n]  (all branches via blockIdx.y)
__global__ void k_meanT_all()
{
    __shared__ float t[32][33];
    int by = blockIdx.y;
    int br = (by >= 2) + (by >= 6) + (by >= 14);
    const int cs[4]    = {64, 128, 256, 512};
    const int ybase[4] = {0, 2, 6, 14};
    const long ctxoff[4] = {0, 64L*64*196, 64L*192*196, 64L*448*196};
    const long cmoff[4]  = {0, 16L*196*64, 16L*196*192, 16L*196*448};
    int c = cs[br];
    int b  = blockIdx.z;
    int d0 = (by - ybase[br]) * 32, n0 = blockIdx.x * 32;
    const float* ctx = g_ctx + ctxoff[br];
    float* cm = g_ctxm + cmoff[br];
    int tx = threadIdx.x, ty = threadIdx.y;
    for (int i = ty; i < 32; i += 8) {
        int d = d0 + i, n = n0 + tx;
        float s = 0.f;
        if (n < 196) {
            for (int hh = 0; hh < 4; hh++)
                s += ctx[((size_t)(b * 4 + hh) * c + d) * 196 + n];
        }
        t[i][tx] = 0.25f * s;
    }
    __syncthreads();
    for (int i = ty; i < 32; i += 8) {
        int n = n0 + i, d = d0 + tx;
        if (n < 196) cm[((size_t)b * 196 + n) * c + d] = t[tx][i];
    }
}

// ---------------- launch -------------------------------------------------------------
extern "C" void kernel_launch(void* const* d_in, const int* in_sizes, int n_in,
                              void* d_out, int out_size)
{
    (void)in_sizes; (void)n_in; (void)out_size;
    const float* emb[4]  = {(const float*)d_in[0], (const float*)d_in[1],
                            (const float*)d_in[2], (const float*)d_in[3]};
    const float* emb_all = (const float*)d_in[4];
    const float* Wq[4]   = {(const float*)d_in[5], (const float*)d_in[6],
                            (const float*)d_in[7], (const float*)d_in[8]};
    const float* Wk      = (const float*)d_in[9];
    const float* Wv      = (const float*)d_in[10];
    const float* Wo[4]   = {(const float*)d_in[11], (const float*)d_in[12],
                            (const float*)d_in[13], (const float*)d_in[14]};
    float* out = (float*)d_out;

    float *pK, *pV, *pQ, *pSc, *pCx, *pCm;
    cudaGetSymbolAddress((void**)&pK,  g_K);
    cudaGetSymbolAddress((void**)&pV,  g_V);
    cudaGetSymbolAddress((void**)&pQ,  g_Q);
    cudaGetSymbolAddress((void**)&pSc, g_scores);
    cudaGetSymbolAddress((void**)&pCx, g_ctx);
    cudaGetSymbolAddress((void**)&pCm, g_ctxm);

    const int   Cs[4]    = {64, 128, 256, 512};
    const int   cumc[4]  = {0, 64, 192, 448};
    const int   my[4]    = {1, 1, 2, 4};            // ceil(c/128)
    const int   rmbase[4]= {0, 4096, 12288, 28672};
    const int   offs[4]  = {0, 16*196*64, 16*196*(64+128), 16*196*(64+128+256)};
    const float SCALE    = 0.03227486121839514f;    // 1/sqrt(960)
    const int   IMAXI    = 0x7fffffff;

    k_initmax<<<(64 * 960 + 255) / 256, 256>>>();

    // ---- ONE merged projection launch: K, V, Q0..Q3 (all per-h, M=3136) ----
    {
        Jobs J = {};
        // job0: K[h][3136][960] = emb_all_flat @ Wk[h]^T
        J.A[0]=emb_all; J.sAh[0]=0; J.sAb[0]=0; J.lda[0]=960;
        J.B[0]=Wk; J.sBh[0]=960L*960; J.sBb[0]=0; J.ldb[0]=960;
        J.C[0]=pK; J.sCh[0]=3136L*960; J.sCb[0]=0; J.ldc[0]=960;
        J.M[0]=3136; J.N[0]=960; J.K[0]=960; J.alpha[0]=1.f; J.nx[0]=8; J.bx0[0]=0;
        // job1: V[h][3136][960] = emb_all_flat @ Wv[h]^T
        J.A[1]=emb_all; J.sAh[1]=0; J.sAb[1]=0; J.lda[1]=960;
        J.B[1]=Wv; J.sBh[1]=960L*960; J.sBb[1]=0; J.ldb[1]=960;
        J.C[1]=pV; J.sCh[1]=3136L*960; J.sCb[1]=0; J.ldc[1]=960;
        J.M[1]=3136; J.N[1]=960; J.K[1]=960; J.alpha[1]=1.f; J.nx[1]=8; J.bx0[1]=200;
        // jobs 2..5: Q_br[h][3136][c] = emb_br_flat @ Wq_br[h]^T
        int bx = 400;
        for (int br = 0; br < 4; br++) {
            long c = Cs[br];
            int s = 2 + br;
            J.A[s]=emb[br]; J.sAh[s]=0; J.sAb[s]=0; J.lda[s]=(int)c;
            J.B[s]=Wq[br];  J.sBh[s]=c*c; J.sBb[s]=0; J.ldb[s]=(int)c;
            J.C[s]=pQ + 4L*3136*cumc[br];
            J.sCh[s]=3136L*c; J.sCb[s]=0; J.ldc[s]=(int)c;
            J.M[s]=3136; J.N[s]=(int)c; J.K[s]=(int)c; J.alpha[s]=1.f;
            int nxq = (Cs[br] + 127) / 128;          // {1,1,2,4}
            J.nx[s]=nxq; J.bx0[s]=bx; bx += 25 * nxq;
        }
        for (int s = 6; s < NJ; s++) J.bx0[s] = IMAXI;
        k_gemm_abT<<<dim3(600, 1, 4), 256>>>(J);     // bx total = 600
    }

    // ---- merged scores GEMM (A^T form) + stats epilogue (4 jobs, z=64) ----
    {
        Jobs J = {};
        int bx = 0;
        for (int br = 0; br < 4; br++) {
            long c = Cs[br];
            J.A[br]=pQ + 4L*3136*cumc[br];           // [h][3136][c], slice [196,c]
            J.sAh[br]=3136L*c; J.sAb[br]=196L*c; J.lda[br]=(int)c;
            J.B[br]=pK;                               // [h][3136][960], slice [196,960]
            J.sBh[br]=3136L*960; J.sBb[br]=196L*960; J.ldb[br]=960;
            J.C[br]=pSc + 64L*960*cumc[br];
            J.sCh[br]=c*960; J.sCb[br]=4L*c*960; J.ldc[br]=960;
            J.M[br]=(int)c; J.N[br]=960; J.K[br]=196; J.alpha[br]=SCALE;
            J.nx[br]=8; J.bx0[br]=bx; J.rmoff[br]=rmbase[br]; bx += 8 * my[br];
        }
        for (int s = 4; s < NJ; s++) J.bx0[s] = IMAXI;
        k_gemm_aTb_stats<<<dim3(64, 1, 64), 256>>>(J);
    }

    k_stats_final<<<1, 256>>>();
    k_probs<<<61440, 256>>>();

    // ---- merged ctx GEMM: C = probs * Vslice^T (4 jobs, z=64) ----
    {
        Jobs J = {};
        int bx = 0;
        for (int br = 0; br < 4; br++) {
            long c = Cs[br];
            J.A[br]=pSc + 64L*960*cumc[br];
            J.sAh[br]=c*960; J.sAb[br]=4L*c*960; J.lda[br]=960;
            J.B[br]=pV;                               // [h][3136][960], slice [196,960]
            J.sBh[br]=3136L*960; J.sBb[br]=196L*960; J.ldb[br]=960;
            J.C[br]=pCx + 64L*196*cumc[br];
            J.sCh[br]=c*196; J.sCb[br]=4L*c*196; J.ldc[br]=196;
            J.M[br]=(int)c; J.N[br]=196; J.K[br]=960; J.alpha[br]=1.f;
            J.nx[br]=2; J.bx0[br]=bx; bx += 2 * my[br];
        }
        for (int s = 4; s < NJ; s++) J.bx0[s] = IMAXI;
        k_gemm_abT<<<dim3(16, 1, 64), 256>>>(J);
    }

    k_meanT_all<<<dim3(7, 30, 16), dim3(32, 8)>>>();

    // ---- merged output projections (4 jobs, z=1) ----
    {
        Jobs J = {};
        int bx = 0;
        for (int br = 0; br < 4; br++) {
            long c = Cs[br];
            J.A[br]=pCm + 16L*196*cumc[br];
            J.sAh[br]=0; J.sAb[br]=0; J.lda[br]=(int)c;
            J.B[br]=Wo[br]; J.sBh[br]=0; J.sBb[br]=0; J.ldb[br]=(int)c;
            J.C[br]=out + offs[br]; J.sCh[br]=0; J.sCb[br]=0; J.ldc[br]=(int)c;
            J.M[br]=16*196; J.N[br]=(int)c; J.K[br]=(int)c; J.alpha[br]=1.f;
            int nxo = (Cs[br] + 127) / 128;
            J.nx[br]=nxo; J.bx0[br]=bx; bx += nxo * 25;
        }
        for (int s = 4; s < NJ; s++) J.bx0[s] = IMAXI;
        k_gemm_abT<<<dim3(200, 1, 1), 256>>>(J);
    }
}